// round 11
// baseline (speedup 1.0000x reference)
#include <cuda_runtime.h>
#include <cuda_fp16.h>
#include <cstdint>

#define BATCH 8
#define SEQ   4096
#define DIM   256
#define SPLITK 8
#define SCHUNK (SEQ/SPLITK)   // 512
#define KC 32                 // k-chunk GEMM1 (tf32)
#define KC2 64                // k-chunk GEMM2 (fp16)

// Scratch (no allocs allowed -> __device__ globals)
__device__ float  g_KVp[SPLITK*BATCH*DIM*DIM]; // split-K partials [sp][b][d][e]
__device__ __half g_KVTh[BATCH*DIM*DIM];       // KV^T as half: [b][e][d]
__device__ float  g_ksp[BATCH*SPLITK*DIM];     // k_sum split partials
__device__ float  g_ks [BATCH*DIM];            // k_sum[b][d]

__device__ __forceinline__ float phi(float x){
    // sigmoid(0.6053*x - 4.102) = 1/(1+exp(4.102 - 0.6053*x))
    return 1.0f / (1.0f + __expf(4.102f - 0.6053f * x));
}
__device__ __forceinline__ uint32_t to_tf32(float x){
    uint32_t r; asm("cvt.rna.tf32.f32 %0, %1;" : "=r"(r) : "f"(x)); return r;
}
__device__ __forceinline__ uint32_t f2tf(uint32_t raw){
    return to_tf32(__uint_as_float(raw));
}
__device__ __forceinline__ uint32_t pkh(float lo, float hi){
    __half2 h = __halves2half2(__float2half_rn(lo), __float2half_rn(hi));
    return *(uint32_t*)&h;
}
__device__ __forceinline__ void mma8(float c[4], const uint32_t a[4],
                                     uint32_t b0, uint32_t b1){
    asm volatile("mma.sync.aligned.m16n8k8.row.col.f32.tf32.tf32.f32 "
        "{%0,%1,%2,%3},{%4,%5,%6,%7},{%8,%9},{%0,%1,%2,%3};"
        : "+f"(c[0]),"+f"(c[1]),"+f"(c[2]),"+f"(c[3])
        : "r"(a[0]),"r"(a[1]),"r"(a[2]),"r"(a[3]),"r"(b0),"r"(b1));
}
__device__ __forceinline__ void mma16h(float c[4], const uint32_t a[4],
                                       uint32_t b0, uint32_t b1){
    asm volatile("mma.sync.aligned.m16n8k16.row.col.f32.f16.f16.f32 "
        "{%0,%1,%2,%3},{%4,%5,%6,%7},{%8,%9},{%0,%1,%2,%3};"
        : "+f"(c[0]),"+f"(c[1]),"+f"(c[2]),"+f"(c[3])
        : "r"(a[0]),"r"(a[1]),"r"(a[2]),"r"(a[3]),"r"(b0),"r"(b1));
}
__device__ __forceinline__ uint32_t smem_u32(const void* p){
    uint32_t a;
    asm("{ .reg .u64 t; cvta.to.shared.u64 t, %1; cvt.u32.u64 %0, t; }" : "=r"(a) : "l"(p));
    return a;
}
__device__ __forceinline__ void cp16(uint32_t dst, const void* src){
    asm volatile("cp.async.ca.shared.global [%0], [%1], 16;" :: "r"(dst), "l"(src));
}
__device__ __forceinline__ void cp_commit(){ asm volatile("cp.async.commit_group;"); }
__device__ __forceinline__ void cp_wait0(){ asm volatile("cp.async.wait_group 0;"); }

// ---------------------------------------------------------------------------
// GEMM 1 (tf32 mma, split-K): KVp[sp][b][d][e] += phi(K[b][s][d]) * V[b][s][e]
// [unchanged from R9]
// ---------------------------------------------------------------------------
#define G1_OFF_A  0
#define G1_OFF_B  34816
#define G1_OFF_KS 69632
#define G1_SMEM   73728

__global__ __launch_bounds__(256,2) void kv_part_kernel(const float* __restrict__ K,
                                                        const float* __restrict__ V){
    extern __shared__ char smraw[];
    uint32_t (*As)[KC][136] = (uint32_t(*)[KC][136])(smraw + G1_OFF_A);
    uint32_t (*Bs)[KC][136] = (uint32_t(*)[KC][136])(smraw + G1_OFF_B);
    float* ksred = (float*)(smraw + G1_OFF_KS);

    int b = blockIdx.z, sp = blockIdx.y;
    int dt = blockIdx.x >> 1, et = blockIdx.x & 1;
    int t = threadIdx.x, lane = t & 31, w = t >> 5;
    int wm = (w & 1)*64, wn = (w >> 1)*32;
    int gid = lane >> 2, tig = lane & 3;

    const float* Kb = K + ((size_t)b*SEQ + (size_t)sp*SCHUNK)*DIM + dt*128;
    const float* Vb = V + ((size_t)b*SEQ + (size_t)sp*SCHUNK)*DIM + et*128;

    int col4 = lane*4;
    float ksum_p[4] = {};
    float4 kreg[4];

    #pragma unroll
    for (int p = 0; p < 4; p++){
        kreg[p] = *(const float4*)(Kb + (size_t)(w+8*p)*DIM + col4);
        cp16(smem_u32(&Bs[0][w+8*p][col4]), Vb + (size_t)(w+8*p)*DIM + col4);
    }
    cp_commit();
    #pragma unroll
    for (int p = 0; p < 4; p++){
        float f0=phi(kreg[p].x), f1=phi(kreg[p].y), f2=phi(kreg[p].z), f3=phi(kreg[p].w);
        ksum_p[0]+=f0; ksum_p[1]+=f1; ksum_p[2]+=f2; ksum_p[3]+=f3;
        uint4 u = { to_tf32(f0), to_tf32(f1), to_tf32(f2), to_tf32(f3) };
        *(uint4*)&As[0][w+8*p][col4] = u;
    }
    cp_wait0();
    __syncthreads();

    float acc[4][4][4] = {};
    int stage = 0;
    for (int k0 = 0; k0 < SCHUNK; k0 += KC){
        int nxt = stage ^ 1;
        bool hn = (k0 + KC) < SCHUNK;
        if (hn){
            #pragma unroll
            for (int p = 0; p < 4; p++){
                kreg[p] = *(const float4*)(Kb + (size_t)(k0+KC+w+8*p)*DIM + col4);
                cp16(smem_u32(&Bs[nxt][w+8*p][col4]),
                     Vb + (size_t)(k0+KC+w+8*p)*DIM + col4);
            }
            cp_commit();
        }
        #pragma unroll
        for (int kk = 0; kk < KC; kk += 8){
            uint32_t bf[4][2];
            #pragma unroll
            for (int ni = 0; ni < 4; ni++){
                int n = wn + ni*8 + gid;
                bf[ni][0] = f2tf(Bs[stage][kk+tig  ][n]);
                bf[ni][1] = f2tf(Bs[stage][kk+tig+4][n]);
            }
            uint32_t af[4][4];
            #pragma unroll
            for (int mi = 0; mi < 4; mi++){
                int m = wm + mi*16 + gid;
                af[mi][0] = As[stage][kk+tig  ][m  ];
                af[mi][1] = As[stage][kk+tig  ][m+8];
                af[mi][2] = As[stage][kk+tig+4][m  ];
                af[mi][3] = As[stage][kk+tig+4][m+8];
            }
            #pragma unroll
            for (int mi = 0; mi < 4; mi++)
                #pragma unroll
                for (int ni = 0; ni < 4; ni++)
                    mma8(acc[mi][ni], af[mi], bf[ni][0], bf[ni][1]);
        }
        if (hn){
            #pragma unroll
            for (int p = 0; p < 4; p++){
                float f0=phi(kreg[p].x), f1=phi(kreg[p].y), f2=phi(kreg[p].z), f3=phi(kreg[p].w);
                ksum_p[0]+=f0; ksum_p[1]+=f1; ksum_p[2]+=f2; ksum_p[3]+=f3;
                uint4 u = { to_tf32(f0), to_tf32(f1), to_tf32(f2), to_tf32(f3) };
                *(uint4*)&As[nxt][w+8*p][col4] = u;
            }
        }
        cp_wait0();
        __syncthreads();
        stage = nxt;
    }

    *(float4*)&ksred[w*128 + col4] = make_float4(ksum_p[0],ksum_p[1],ksum_p[2],ksum_p[3]);
    __syncthreads();
    if (et == 0 && t < 128){
        float s = 0.f;
        #pragma unroll
        for (int g = 0; g < 8; g++) s += ksred[g*128 + t];
        g_ksp[(b*SPLITK + sp)*DIM + dt*128 + t] = s;
    }

    float* outp = g_KVp + (((size_t)sp*BATCH + b)*DIM + dt*128)*DIM + et*128;
    #pragma unroll
    for (int mi = 0; mi < 4; mi++)
        #pragma unroll
        for (int ni = 0; ni < 4; ni++){
            int r = wm + mi*16 + gid, c = wn + ni*8 + tig*2;
            float2 v0 = {acc[mi][ni][0], acc[mi][ni][1]};
            float2 v1 = {acc[mi][ni][2], acc[mi][ni][3]};
            *(float2*)(outp + (size_t)r*DIM + c)     = v0;
            *(float2*)(outp + (size_t)(r+8)*DIM + c) = v1;
        }
}

__global__ __launch_bounds__(256) void ksum_reduce_kernel(){
    int i = blockIdx.x*256 + threadIdx.x;
    int b = i / DIM, d = i % DIM;
    float acc = 0.f;
    #pragma unroll
    for (int sp = 0; sp < SPLITK; sp++) acc += g_ksp[(b*SPLITK + sp)*DIM + d];
    g_ks[i] = acc;
}

// ---------------------------------------------------------------------------
// kv_reduceT: sum split-K partials, TRANSPOSE, convert to half.
// g_KVTh[b][e][d] = (half) sum_sp KVp[sp][b][d][e].  64x64 smem tiles.
// ---------------------------------------------------------------------------
__global__ __launch_bounds__(256) void kv_reduceT_kernel(){
    __shared__ float sm[64][65];
    int b = blockIdx.y;
    int td = (blockIdx.x & 3)*64, te = (blockIdx.x >> 2)*64;
    int t = threadIdx.x;
    #pragma unroll
    for (int p = 0; p < 16; p++){
        int idx = t + p*256;
        int r = idx >> 6, c = idx & 63;       // r: d-local, c: e-local
        float acc = 0.f;
        size_t base = ((size_t)b*DIM + td + r)*DIM + te + c;
        #pragma unroll
        for (int sp = 0; sp < SPLITK; sp++)
            acc += g_KVp[(size_t)sp*BATCH*DIM*DIM + base];
        sm[r][c] = acc;
    }
    __syncthreads();
    #pragma unroll
    for (int p = 0; p < 16; p++){
        int idx = t + p*256;
        int r = idx >> 6, c = idx & 63;       // r: e-local, c: d-local
        g_KVTh[((size_t)b*DIM + te + r)*DIM + td + c] = __float2half_rn(sm[c][r]);
    }
}

// ---------------------------------------------------------------------------
// GEMM 2 (fp16 mma.m16n8k16): Out[b][s][e] = (phi(Q).KV)/(phi(Q).k_sum)
// CTA tile 128(s)x128(e), 8 warps 64x32, KC2=64 double buffered (4 chunks).
// A = phi(Q) half [m][k] stride 36 words; B = KV^T half [n][k] via cp.async.
// Stage stride for B cp.async FIXED: 128*36*4 = 18432 bytes (was 36864 -> OOB).
// grid (2, 32, 8) = 512 CTAs, 2 CTAs/SM.
// ---------------------------------------------------------------------------
#define G2_OFF_A    0                    // 2*128*36*4 = 36864
#define G2_OFF_B    36864                // 2*128*36*4 = 36864
#define B_STG       18432                // one B stage in bytes
#define G2_OFF_INVB 73728                // 512
#define G2_OFF_KS   74240                // 1024
#define G2_SMEM     75264

__global__ __launch_bounds__(256,2) void out_kernel(const float* __restrict__ Q,
                                                    float* __restrict__ Out){
    extern __shared__ char smraw[];
    uint32_t (*As)[128][36] = (uint32_t(*)[128][36])(smraw + G2_OFF_A);
    uint32_t (*Bs)[128][36] = (uint32_t(*)[128][36])(smraw + G2_OFF_B);
    float* invb = (float*)(smraw + G2_OFF_INVB);
    float* ks_s = (float*)(smraw + G2_OFF_KS);

    int et = blockIdx.x, st = blockIdx.y, b = blockIdx.z;
    int t = threadIdx.x, lane = t & 31, w = t >> 5;
    int wm = (w & 1)*64, wn = (w >> 1)*32;
    int gid = lane >> 2, tig = lane & 3;

    const float* Qb = Q + ((size_t)b*SEQ + st*128)*DIM;
    const __half* KVTb = g_KVTh + ((size_t)b*DIM + et*128)*DIM;

    ks_s[t] = g_ks[b*DIM + t];

    int a_row = t >> 1, a_kb = (t & 1)*32;   // A: row a_row, 32 k-halves
    int b_row = t >> 1, b_sb = (t & 1)*4;    // B: row, 4 x 16B segments
    uint32_t bs_base = smem_u32(smraw + G2_OFF_B);
    float bot_p = 0.f;
    float4 qreg[8];

    // ---- prologue: chunk 0 ----
    #pragma unroll
    for (int j = 0; j < 8; j++)
        qreg[j] = *(const float4*)(Qb + (size_t)a_row*DIM + a_kb + j*4);
    #pragma unroll
    for (int j = 0; j < 4; j++)
        cp16(bs_base + b_row*144 + (b_sb + j)*16,
             KVTb + (size_t)b_row*DIM + (b_sb + j)*8);
    cp_commit();
    __syncthreads();            // ks_s visible
    #pragma unroll
    for (int j = 0; j < 8; j++){
        float f0=phi(qreg[j].x), f1=phi(qreg[j].y), f2=phi(qreg[j].z), f3=phi(qreg[j].w);
        int k = a_kb + j*4;
        bot_p += f0*ks_s[k] + f1*ks_s[k+1] + f2*ks_s[k+2] + f3*ks_s[k+3];
        As[0][a_row][(a_kb>>1) + j*2    ] = pkh(f0, f1);
        As[0][a_row][(a_kb>>1) + j*2 + 1] = pkh(f2, f3);
    }
    cp_wait0();
    __syncthreads();

    float acc[4][4][4] = {};
    int stage = 0;
    for (int k0 = 0; k0 < DIM; k0 += KC2){
        int nxt = stage ^ 1;
        bool hn = (k0 + KC2) < DIM;
        if (hn){
            #pragma unroll
            for (int j = 0; j < 8; j++)
                qreg[j] = *(const float4*)(Qb + (size_t)a_row*DIM + k0 + KC2 + a_kb + j*4);
            #pragma unroll
            for (int j = 0; j < 4; j++)
                cp16(bs_base + nxt*B_STG + b_row*144 + (b_sb + j)*16,
                     KVTb + (size_t)b_row*DIM + k0 + KC2 + (b_sb + j)*8);
            cp_commit();
        }
        // 4 k16-steps per chunk
        #pragma unroll
        for (int kk = 0; kk < 4; kk++){
            uint32_t bf[4][2];
            #pragma unroll
            for (int ni = 0; ni < 4; ni++){
                int n = wn + ni*8 + gid;
                bf[ni][0] = Bs[stage][n][kk*8 + tig    ];
                bf[ni][1] = Bs[stage][n][kk*8 + tig + 4];
            }
            uint32_t af[4][4];
            #pragma unroll
            for (int mi = 0; mi < 4; mi++){
                int m = wm + mi*16 + gid;
                af[mi][0] = As[stage][m  ][kk*8 + tig    ];
                af[mi][1] = As[stage][m+8][kk*8 + tig    ];
                af[mi][2] = As[stage][m  ][kk*8 + tig + 4];
                af[mi][3] = As[stage][m+8][kk*8 + tig + 4];
            }
            #pragma unroll
            for (int mi = 0; mi < 4; mi++)
                #pragma unroll
                for (int ni = 0; ni < 4; ni++)
                    mma16h(acc[mi][ni], af[mi], bf[ni][0], bf[ni][1]);
        }
        if (hn){
            #pragma unroll
            for (int j = 0; j < 8; j++){
                float f0=phi(qreg[j].x), f1=phi(qreg[j].y), f2=phi(qreg[j].z), f3=phi(qreg[j].w);
                int k = k0 + KC2 + a_kb + j*4;
                bot_p += f0*ks_s[k] + f1*ks_s[k+1] + f2*ks_s[k+2] + f3*ks_s[k+3];
                As[nxt][a_row][(a_kb>>1) + j*2    ] = pkh(f0, f1);
                As[nxt][a_row][(a_kb>>1) + j*2 + 1] = pkh(f2, f3);
            }
        }
        cp_wait0();
        __syncthreads();
        stage = nxt;
    }

    // fused bottom: threads t, t^1 share row a_row
    bot_p += __shfl_xor_sync(0xffffffffu, bot_p, 1);
    if ((t & 1) == 0) invb[a_row] = 1.0f / bot_p;
    __syncthreads();

    float* outp = Out + ((size_t)b*SEQ + st*128)*DIM + et*128;
    #pragma unroll
    for (int mi = 0; mi < 4; mi++)
        #pragma unroll
        for (int ni = 0; ni < 4; ni++){
            int r = wm + mi*16 + gid, c = wn + ni*8 + tig*2;
            float ib0 = invb[r], ib1 = invb[r+8];
            float2 v0 = {acc[mi][ni][0]*ib0, acc[mi][ni][1]*ib0};
            float2 v1 = {acc[mi][ni][2]*ib1, acc[mi][ni][3]*ib1};
            *(float2*)(outp + (size_t)r*DIM + c)     = v0;
            *(float2*)(outp + (size_t)(r+8)*DIM + c) = v1;
        }
}

// ---------------------------------------------------------------------------
extern "C" void kernel_launch(void* const* d_in, const int* in_sizes, int n_in,
                              void* d_out, int out_size){
    const float* Q = (const float*)d_in[0];
    const float* K = (const float*)d_in[1];
    const float* V = (const float*)d_in[2];
    float* Out = (float*)d_out;

    cudaFuncSetAttribute(kv_part_kernel,
                         cudaFuncAttributeMaxDynamicSharedMemorySize, G1_SMEM);
    cudaFuncSetAttribute(out_kernel,
                         cudaFuncAttributeMaxDynamicSharedMemorySize, G2_SMEM);

    kv_part_kernel    <<<dim3(4, SPLITK, BATCH), 256, G1_SMEM>>>(K, V);
    ksum_reduce_kernel<<<(BATCH*DIM)/256, 256>>>();
    kv_reduceT_kernel <<<dim3(16, BATCH), 256>>>();
    out_kernel        <<<dim3(2, 32, BATCH), 256, G2_SMEM>>>(Q, Out);
}

// round 13
// speedup vs baseline: 1.3407x; 1.3407x over previous
#include <cuda_runtime.h>
#include <cuda_fp16.h>
#include <cstdint>

#define BATCH 8
#define SEQ   4096
#define DIM   256
#define SPLITK 8
#define SCHUNK (SEQ/SPLITK)   // 512
#define KC 32                 // k-chunk GEMM1 (tf32)
#define KC2 64                // k-chunk GEMM2 (fp16)

// Scratch (no allocs allowed -> __device__ globals)
__device__ float  g_KVp[SPLITK*BATCH*DIM*DIM]; // split-K partials [sp][b][d][e]
__device__ __half g_KVTh[BATCH*DIM*DIM];       // KV^T as half: [b][e][d]
__device__ __half g_phiQh[BATCH*SEQ*DIM];      // phi(Q) as half: [b][s][d]
__device__ float  g_invb[BATCH*SEQ];           // 1/bottom per row
__device__ float  g_ksp[BATCH*SPLITK*DIM];     // k_sum split partials
__device__ float  g_ks [BATCH*DIM];            // k_sum[b][d]

__device__ __forceinline__ float phi(float x){
    // sigmoid(0.6053*x - 4.102) = 1/(1+exp(4.102 - 0.6053*x)); fast division
    return __fdividef(1.0f, 1.0f + __expf(4.102f - 0.6053f * x));
}
__device__ __forceinline__ uint32_t to_tf32(float x){
    uint32_t r; asm("cvt.rna.tf32.f32 %0, %1;" : "=r"(r) : "f"(x)); return r;
}
__device__ __forceinline__ uint32_t f2tf(uint32_t raw){
    return to_tf32(__uint_as_float(raw));
}
__device__ __forceinline__ void mma8(float c[4], const uint32_t a[4],
                                     uint32_t b0, uint32_t b1){
    asm volatile("mma.sync.aligned.m16n8k8.row.col.f32.tf32.tf32.f32 "
        "{%0,%1,%2,%3},{%4,%5,%6,%7},{%8,%9},{%0,%1,%2,%3};"
        : "+f"(c[0]),"+f"(c[1]),"+f"(c[2]),"+f"(c[3])
        : "r"(a[0]),"r"(a[1]),"r"(a[2]),"r"(a[3]),"r"(b0),"r"(b1));
}
__device__ __forceinline__ void mma16h(float c[4], const uint32_t a[4],
                                       uint32_t b0, uint32_t b1){
    asm volatile("mma.sync.aligned.m16n8k16.row.col.f32.f16.f16.f32 "
        "{%0,%1,%2,%3},{%4,%5,%6,%7},{%8,%9},{%0,%1,%2,%3};"
        : "+f"(c[0]),"+f"(c[1]),"+f"(c[2]),"+f"(c[3])
        : "r"(a[0]),"r"(a[1]),"r"(a[2]),"r"(a[3]),"r"(b0),"r"(b1));
}
__device__ __forceinline__ uint32_t smem_u32(const void* p){
    uint32_t a;
    asm("{ .reg .u64 t; cvta.to.shared.u64 t, %1; cvt.u32.u64 %0, t; }" : "=r"(a) : "l"(p));
    return a;
}
__device__ __forceinline__ void cp16(uint32_t dst, const void* src){
    asm volatile("cp.async.ca.shared.global [%0], [%1], 16;" :: "r"(dst), "l"(src));
}
__device__ __forceinline__ void cp_commit(){ asm volatile("cp.async.commit_group;"); }
__device__ __forceinline__ void cp_wait0(){ asm volatile("cp.async.wait_group 0;"); }

// ---------------------------------------------------------------------------
// GEMM 1 (tf32 mma, split-K): KVp[sp][b][d][e] += phi(K[b][s][d]) * V[b][s][e]
// [structure unchanged from R9/R11; phi uses fast division]
// ---------------------------------------------------------------------------
#define G1_OFF_A  0
#define G1_OFF_B  34816
#define G1_OFF_KS 69632
#define G1_SMEM   73728

__global__ __launch_bounds__(256,2) void kv_part_kernel(const float* __restrict__ K,
                                                        const float* __restrict__ V){
    extern __shared__ char smraw[];
    uint32_t (*As)[KC][136] = (uint32_t(*)[KC][136])(smraw + G1_OFF_A);
    uint32_t (*Bs)[KC][136] = (uint32_t(*)[KC][136])(smraw + G1_OFF_B);
    float* ksred = (float*)(smraw + G1_OFF_KS);

    int b = blockIdx.z, sp = blockIdx.y;
    int dt = blockIdx.x >> 1, et = blockIdx.x & 1;
    int t = threadIdx.x, lane = t & 31, w = t >> 5;
    int wm = (w & 1)*64, wn = (w >> 1)*32;
    int gid = lane >> 2, tig = lane & 3;

    const float* Kb = K + ((size_t)b*SEQ + (size_t)sp*SCHUNK)*DIM + dt*128;
    const float* Vb = V + ((size_t)b*SEQ + (size_t)sp*SCHUNK)*DIM + et*128;

    int col4 = lane*4;
    float ksum_p[4] = {};
    float4 kreg[4];

    #pragma unroll
    for (int p = 0; p < 4; p++){
        kreg[p] = *(const float4*)(Kb + (size_t)(w+8*p)*DIM + col4);
        cp16(smem_u32(&Bs[0][w+8*p][col4]), Vb + (size_t)(w+8*p)*DIM + col4);
    }
    cp_commit();
    #pragma unroll
    for (int p = 0; p < 4; p++){
        float f0=phi(kreg[p].x), f1=phi(kreg[p].y), f2=phi(kreg[p].z), f3=phi(kreg[p].w);
        ksum_p[0]+=f0; ksum_p[1]+=f1; ksum_p[2]+=f2; ksum_p[3]+=f3;
        uint4 u = { to_tf32(f0), to_tf32(f1), to_tf32(f2), to_tf32(f3) };
        *(uint4*)&As[0][w+8*p][col4] = u;
    }
    cp_wait0();
    __syncthreads();

    float acc[4][4][4] = {};
    int stage = 0;
    for (int k0 = 0; k0 < SCHUNK; k0 += KC){
        int nxt = stage ^ 1;
        bool hn = (k0 + KC) < SCHUNK;
        if (hn){
            #pragma unroll
            for (int p = 0; p < 4; p++){
                kreg[p] = *(const float4*)(Kb + (size_t)(k0+KC+w+8*p)*DIM + col4);
                cp16(smem_u32(&Bs[nxt][w+8*p][col4]),
                     Vb + (size_t)(k0+KC+w+8*p)*DIM + col4);
            }
            cp_commit();
        }
        #pragma unroll
        for (int kk = 0; kk < KC; kk += 8){
            uint32_t bf[4][2];
            #pragma unroll
            for (int ni = 0; ni < 4; ni++){
                int n = wn + ni*8 + gid;
                bf[ni][0] = f2tf(Bs[stage][kk+tig  ][n]);
                bf[ni][1] = f2tf(Bs[stage][kk+tig+4][n]);
            }
            uint32_t af[4][4];
            #pragma unroll
            for (int mi = 0; mi < 4; mi++){
                int m = wm + mi*16 + gid;
                af[mi][0] = As[stage][kk+tig  ][m  ];
                af[mi][1] = As[stage][kk+tig  ][m+8];
                af[mi][2] = As[stage][kk+tig+4][m  ];
                af[mi][3] = As[stage][kk+tig+4][m+8];
            }
            #pragma unroll
            for (int mi = 0; mi < 4; mi++)
                #pragma unroll
                for (int ni = 0; ni < 4; ni++)
                    mma8(acc[mi][ni], af[mi], bf[ni][0], bf[ni][1]);
        }
        if (hn){
            #pragma unroll
            for (int p = 0; p < 4; p++){
                float f0=phi(kreg[p].x), f1=phi(kreg[p].y), f2=phi(kreg[p].z), f3=phi(kreg[p].w);
                ksum_p[0]+=f0; ksum_p[1]+=f1; ksum_p[2]+=f2; ksum_p[3]+=f3;
                uint4 u = { to_tf32(f0), to_tf32(f1), to_tf32(f2), to_tf32(f3) };
                *(uint4*)&As[nxt][w+8*p][col4] = u;
            }
        }
        cp_wait0();
        __syncthreads();
        stage = nxt;
    }

    *(float4*)&ksred[w*128 + col4] = make_float4(ksum_p[0],ksum_p[1],ksum_p[2],ksum_p[3]);
    __syncthreads();
    if (et == 0 && t < 128){
        float s = 0.f;
        #pragma unroll
        for (int g = 0; g < 8; g++) s += ksred[g*128 + t];
        g_ksp[(b*SPLITK + sp)*DIM + dt*128 + t] = s;
    }

    float* outp = g_KVp + (((size_t)sp*BATCH + b)*DIM + dt*128)*DIM + et*128;
    #pragma unroll
    for (int mi = 0; mi < 4; mi++)
        #pragma unroll
        for (int ni = 0; ni < 4; ni++){
            int r = wm + mi*16 + gid, c = wn + ni*8 + tig*2;
            float2 v0 = {acc[mi][ni][0], acc[mi][ni][1]};
            float2 v1 = {acc[mi][ni][2], acc[mi][ni][3]};
            *(float2*)(outp + (size_t)r*DIM + c)     = v0;
            *(float2*)(outp + (size_t)(r+8)*DIM + c) = v1;
        }
}

__global__ __launch_bounds__(256) void ksum_reduce_kernel(){
    int i = blockIdx.x*256 + threadIdx.x;
    int b = i / DIM, d = i % DIM;
    float acc = 0.f;
    #pragma unroll
    for (int sp = 0; sp < SPLITK; sp++) acc += g_ksp[(b*SPLITK + sp)*DIM + d];
    g_ks[i] = acc;
}

// ---------------------------------------------------------------------------
// kv_reduceT: sum split-K partials, TRANSPOSE, convert to half.
// ---------------------------------------------------------------------------
__global__ __launch_bounds__(256) void kv_reduceT_kernel(){
    __shared__ float sm[64][65];
    int b = blockIdx.y;
    int td = (blockIdx.x & 3)*64, te = (blockIdx.x >> 2)*64;
    int t = threadIdx.x;
    #pragma unroll
    for (int p = 0; p < 16; p++){
        int idx = t + p*256;
        int r = idx >> 6, c = idx & 63;
        float acc = 0.f;
        size_t base = ((size_t)b*DIM + td + r)*DIM + te + c;
        #pragma unroll
        for (int sp = 0; sp < SPLITK; sp++)
            acc += g_KVp[(size_t)sp*BATCH*DIM*DIM + base];
        sm[r][c] = acc;
    }
    __syncthreads();
    #pragma unroll
    for (int p = 0; p < 16; p++){
        int idx = t + p*256;
        int r = idx >> 6, c = idx & 63;
        g_KVTh[((size_t)b*DIM + te + r)*DIM + td + c] = __float2half_rn(sm[c][r]);
    }
}

// ---------------------------------------------------------------------------
// phiq: streaming precompute. g_phiQh[b][s][d] = half(phi(Q)); g_invb[b][s]
// = 1 / (phi(Q[s,:]) . k_sum[b]).  One warp per row; high occupancy.
// ---------------------------------------------------------------------------
__global__ __launch_bounds__(256) void phiq_kernel(const float* __restrict__ Q){
    __shared__ float ks_s[DIM];
    int b = blockIdx.y;
    int t = threadIdx.x, lane = t & 31, w = t >> 5;
    ks_s[t] = g_ks[b*DIM + t];
    __syncthreads();

    int s = blockIdx.x*8 + w;
    const float* Qp = Q + ((size_t)b*SEQ + s)*DIM;
    __half* Hp = g_phiQh + ((size_t)b*SEQ + s)*DIM;
    float acc = 0.f;
    #pragma unroll
    for (int j = 0; j < 2; j++){
        int d = (lane + j*32)*4;
        float4 q = *(const float4*)(Qp + d);
        float f0=phi(q.x), f1=phi(q.y), f2=phi(q.z), f3=phi(q.w);
        acc += f0*ks_s[d] + f1*ks_s[d+1] + f2*ks_s[d+2] + f3*ks_s[d+3];
        __half2 h01 = __halves2half2(__float2half_rn(f0), __float2half_rn(f1));
        __half2 h23 = __halves2half2(__float2half_rn(f2), __float2half_rn(f3));
        uint2 u = { *(uint32_t*)&h01, *(uint32_t*)&h23 };
        *(uint2*)(Hp + d) = u;
    }
    #pragma unroll
    for (int o = 16; o > 0; o >>= 1) acc += __shfl_xor_sync(0xffffffffu, acc, o);
    if (lane == 0) g_invb[b*SEQ + s] = 1.0f / acc;
}

// ---------------------------------------------------------------------------
// GEMM 2 (fp16 mma.m16n8k16) -- PURE GEMM, loader is cp.async only.
// A = g_phiQh [m][k] via cp.async; B = g_KVTh [n][k] via cp.async.
// SMEM row stride 36 words (words 0..31 data) -> frag LDS conflict-free.
// Epilogue scales by g_invb (staged in smem). CTA 128x128, 8 warps 64x32.
// ---------------------------------------------------------------------------
#define O_A     0                    // 2*128*36*4 = 36864
#define O_B     36864                // 2*128*36*4 = 36864
#define STG_B   18432                // one stage in bytes (128*144)
#define O_INVB  73728                // 512
#define O_SMEM  74240

__global__ __launch_bounds__(256,2) void out_kernel(float* __restrict__ Out){
    extern __shared__ char smraw[];
    uint32_t (*As)[128][36] = (uint32_t(*)[128][36])(smraw + O_A);
    uint32_t (*Bs)[128][36] = (uint32_t(*)[128][36])(smraw + O_B);
    float* invb = (float*)(smraw + O_INVB);

    int et = blockIdx.x, st = blockIdx.y, b = blockIdx.z;
    int t = threadIdx.x, lane = t & 31, w = t >> 5;
    int wm = (w & 1)*64, wn = (w >> 1)*32;
    int gid = lane >> 2, tig = lane & 3;

    const __half* Ab = g_phiQh + ((size_t)b*SEQ + st*128)*DIM;
    const __half* Bb = g_KVTh  + ((size_t)b*DIM + et*128)*DIM;

    if (t < 128) invb[t] = g_invb[b*SEQ + st*128 + t];

    int row = t >> 1, sg0 = (t & 1)*4;     // each thread: 1 row, 4 x 16B segs
    uint32_t a_base = smem_u32(smraw + O_A);
    uint32_t b_base = smem_u32(smraw + O_B);

    // ---- prologue: chunk 0 ----
    #pragma unroll
    for (int j = 0; j < 4; j++){
        int sg = sg0 + j;
        cp16(a_base + row*144 + sg*16, Ab + (size_t)row*DIM + sg*8);
        cp16(b_base + row*144 + sg*16, Bb + (size_t)row*DIM + sg*8);
    }
    cp_commit();
    cp_wait0();
    __syncthreads();

    float acc[4][4][4] = {};
    int stage = 0;
    for (int k0 = 0; k0 < DIM; k0 += KC2){
        int nxt = stage ^ 1;
        bool hn = (k0 + KC2) < DIM;
        if (hn){
            #pragma unroll
            for (int j = 0; j < 4; j++){
                int sg = sg0 + j;
                cp16(a_base + nxt*STG_B + row*144 + sg*16,
                     Ab + (size_t)row*DIM + k0 + KC2 + sg*8);
                cp16(b_base + nxt*STG_B + row*144 + sg*16,
                     Bb + (size_t)row*DIM + k0 + KC2 + sg*8);
            }
            cp_commit();
        }
        // 4 k16-steps per chunk
        #pragma unroll
        for (int kk = 0; kk < 4; kk++){
            uint32_t bf[4][2];
            #pragma unroll
            for (int ni = 0; ni < 4; ni++){
                int n = wn + ni*8 + gid;
                bf[ni][0] = Bs[stage][n][kk*8 + tig    ];
                bf[ni][1] = Bs[stage][n][kk*8 + tig + 4];
            }
            uint32_t af[4][4];
            #pragma unroll
            for (int mi = 0; mi < 4; mi++){
                int m = wm + mi*16 + gid;
                af[mi][0] = As[stage][m  ][kk*8 + tig    ];
                af[mi][1] = As[stage][m+8][kk*8 + tig    ];
                af[mi][2] = As[stage][m  ][kk*8 + tig + 4];
                af[mi][3] = As[stage][m+8][kk*8 + tig + 4];
            }
            #pragma unroll
            for (int mi = 0; mi < 4; mi++)
                #pragma unroll
                for (int ni = 0; ni < 4; ni++)
                    mma16h(acc[mi][ni], af[mi], bf[ni][0], bf[ni][1]);
        }
        cp_wait0();
        __syncthreads();
        stage = nxt;
    }

    float* outp = Out + ((size_t)b*SEQ + st*128)*DIM + et*128;
    #pragma unroll
    for (int mi = 0; mi < 4; mi++)
        #pragma unroll
        for (int ni = 0; ni < 4; ni++){
            int r = wm + mi*16 + gid, c = wn + ni*8 + tig*2;
            float ib0 = invb[r], ib1 = invb[r+8];
            float2 v0 = {acc[mi][ni][0]*ib0, acc[mi][ni][1]*ib0};
            float2 v1 = {acc[mi][ni][2]*ib1, acc[mi][ni][3]*ib1};
            *(float2*)(outp + (size_t)r*DIM + c)     = v0;
            *(float2*)(outp + (size_t)(r+8)*DIM + c) = v1;
        }
}

// ---------------------------------------------------------------------------
extern "C" void kernel_launch(void* const* d_in, const int* in_sizes, int n_in,
                              void* d_out, int out_size){
    const float* Q = (const float*)d_in[0];
    const float* K = (const float*)d_in[1];
    const float* V = (const float*)d_in[2];
    float* Out = (float*)d_out;

    cudaFuncSetAttribute(kv_part_kernel,
                         cudaFuncAttributeMaxDynamicSharedMemorySize, G1_SMEM);
    cudaFuncSetAttribute(out_kernel,
                         cudaFuncAttributeMaxDynamicSharedMemorySize, O_SMEM);

    kv_part_kernel    <<<dim3(4, SPLITK, BATCH), 256, G1_SMEM>>>(K, V);
    ksum_reduce_kernel<<<(BATCH*DIM)/256, 256>>>();
    kv_reduceT_kernel <<<dim3(16, BATCH), 256>>>();
    phiq_kernel       <<<dim3(SEQ/8, BATCH), 256>>>(Q);
    out_kernel        <<<dim3(2, 32, BATCH), 256, O_SMEM>>>(Out);
}